// round 4
// baseline (speedup 1.0000x reference)
#include <cuda_runtime.h>
#include <cstdint>

#define NN 30000
#define MAX_E 520000
#define NEG_SLOPE 0.2f

// ---------------- scratch: __device__ globals, referenced directly ----------------
__device__ float g_h[NN * 512];      // transformed features (A @ W) for current layer
__device__ float g_feat[NN * 512];   // layer output / next layer input
__device__ float g_asrc[NN * 4];
__device__ float g_adst[NN * 4];
__device__ int   g_deg[NN];
__device__ int   g_fill[NN];
__device__ int   g_rowptr[NN + 1];
__device__ int   g_csr[MAX_E];

static inline int cdiv(int a, int b) { return (a + b - 1) / b; }

// ---------------- CSR build (topology shared by all 4 layers) ----------------
__global__ void k_init_deg(int n) {
    int i = blockIdx.x * blockDim.x + threadIdx.x;
    if (i < n) g_deg[i] = 1;  // self-loop
}

// edge_index is int32 (JAX x64 disabled demotes int64 -> int32).
__global__ void k_count(const int* __restrict__ ei, int E0, int n) {
    int e = blockIdx.x * blockDim.x + threadIdx.x;
    if (e < E0) {
        int dst = ei[E0 + e];
        if ((unsigned)dst < (unsigned)n)       // defensive: never trap
            atomicAdd(&g_deg[dst], 1);
    }
}

__global__ void k_scan(int n) {
    __shared__ int sums[1024];
    int t = threadIdx.x;
    int chunk = (n + 1023) / 1024;
    int start = t * chunk;
    if (start > n) start = n;
    int end = start + chunk; if (end > n) end = n;
    int s = 0;
    for (int i = start; i < end; i++) s += g_deg[i];
    sums[t] = s;
    __syncthreads();
    if (t == 0) {
        int acc = 0;
        for (int i = 0; i < 1024; i++) { int v = sums[i]; sums[i] = acc; acc += v; }
        g_rowptr[n] = acc;
    }
    __syncthreads();
    int acc = sums[t];
    for (int i = start; i < end; i++) { g_rowptr[i] = acc; acc += g_deg[i]; }
}

__global__ void k_place_self(int n) {
    int i = blockIdx.x * blockDim.x + threadIdx.x;
    if (i < n) {
        g_csr[g_rowptr[i]] = i;   // self-loop first
        g_fill[i] = 1;
    }
}

__global__ void k_scatter(const int* __restrict__ ei, int E0, int n) {
    int e = blockIdx.x * blockDim.x + threadIdx.x;
    if (e < E0) {
        int src = ei[e];
        int dst = ei[E0 + e];
        if ((unsigned)dst < (unsigned)n && (unsigned)src < (unsigned)n) {
            int pos = atomicAdd(&g_fill[dst], 1);
            g_csr[g_rowptr[dst] + pos] = src;
        }
    }
}

// ---------------- SGEMM: g_h[M,N] = A[M,K] @ B[K,N] ----------------
// BM=64 BN=64 BK=16, 256 threads, 4x4 per thread.
// A = x input (A_PARAM=true, layer 1) or g_feat (layers 2-4). C = g_h always.
template <bool A_PARAM>
__global__ void __launch_bounds__(256) k_sgemm(
    int M, int N, int K,
    const float* __restrict__ Ap, const float* __restrict__ B)
{
    const float* __restrict__ A = A_PARAM ? Ap : (const float*)g_feat;
    float* __restrict__ C = g_h;

    __shared__ float As[16][64];  // transposed: As[k][m]
    __shared__ float Bs[16][64];

    int t = threadIdx.x;
    int tx = t & 15;       // 0..15  -> N
    int ty = t >> 4;       // 0..15  -> M
    int rowBase = blockIdx.y * 64;
    int colBase = blockIdx.x * 64;

    int aRow  = t >> 2;         // 0..63
    int aCol4 = (t & 3) << 2;   // 0,4,8,12
    int bRow  = t >> 4;         // 0..15
    int bCol4 = (t & 15) << 2;  // 0..60

    float acc[4][4] = {};

    for (int k0 = 0; k0 < K; k0 += 16) {
        int gRow = rowBase + aRow;
        float4 av = make_float4(0.f, 0.f, 0.f, 0.f);
        if (gRow < M)
            av = *(const float4*)(A + (size_t)gRow * K + k0 + aCol4);
        As[aCol4 + 0][aRow] = av.x;
        As[aCol4 + 1][aRow] = av.y;
        As[aCol4 + 2][aRow] = av.z;
        As[aCol4 + 3][aRow] = av.w;
        *(float4*)(&Bs[bRow][bCol4]) =
            *(const float4*)(B + (size_t)(k0 + bRow) * N + colBase + bCol4);
        __syncthreads();

        #pragma unroll
        for (int k = 0; k < 16; k++) {
            float a[4], b[4];
            *(float4*)a = *(const float4*)(&As[k][ty << 2]);
            *(float4*)b = *(const float4*)(&Bs[k][tx << 2]);
            #pragma unroll
            for (int i = 0; i < 4; i++)
                #pragma unroll
                for (int j = 0; j < 4; j++)
                    acc[i][j] += a[i] * b[j];
        }
        __syncthreads();
    }

    #pragma unroll
    for (int i = 0; i < 4; i++) {
        int gr = rowBase + (ty << 2) + i;
        if (gr < M) {
            float4 v = make_float4(acc[i][0], acc[i][1], acc[i][2], acc[i][3]);
            *(float4*)(C + (size_t)gr * N + colBase + (tx << 2)) = v;
        }
    }
}

// ---------------- per-node attention logits: g_asrc/g_adst [N,H] from g_h ----------------
__global__ void k_alphas(const float* __restrict__ a_s, const float* __restrict__ a_d,
                         int N, int H, int C)
{
    int n = blockIdx.x;
    int w = threadIdx.x >> 5;
    int lane = threadIdx.x & 31;
    if (w >= H) return;
    const float* hp = g_h + (size_t)n * H * C + w * C;
    float s1 = 0.f, s2 = 0.f;
    for (int c = lane; c < C; c += 32) {
        float v = hp[c];
        s1 += v * a_s[w * C + c];
        s2 += v * a_d[w * C + c];
    }
    #pragma unroll
    for (int o = 16; o > 0; o >>= 1) {
        s1 += __shfl_down_sync(0xffffffffu, s1, o);
        s2 += __shfl_down_sync(0xffffffffu, s2, o);
    }
    if (lane == 0) {
        g_asrc[n * H + w] = s1;
        g_adst[n * H + w] = s2;
    }
}

// ---------------- fused softmax + aggregate + bias + relu ----------------
// one warp per (node, head); C <= 128 so <=4 accum regs per lane.
// Reads g_h; writes g_feat (TO_OUT=false) or the out param (TO_OUT=true).
template <bool TO_OUT>
__global__ void __launch_bounds__(256) k_aggregate(
    const float* __restrict__ bias, float* __restrict__ outp,
    int N, int H, int C)
{
    float* __restrict__ out = TO_OUT ? outp : (float*)g_feat;
    const float* __restrict__ hfeat = g_h;

    int unit = (blockIdx.x * blockDim.x + threadIdx.x) >> 5;
    int lane = threadIdx.x & 31;
    if (unit >= N * H) return;
    int n = unit / H;
    int hh = unit - n * H;

    int s = g_rowptr[n];
    int e = g_rowptr[n + 1];
    float adn = g_adst[n * H + hh];

    // pass 1: max
    float m = -1e30f;
    for (int k = s; k < e; k++) {
        int src = g_csr[k];
        float ev = g_asrc[src * H + hh] + adn;
        ev = (ev > 0.f) ? ev : NEG_SLOPE * ev;
        m = fmaxf(m, ev);
    }

    // pass 2: exp-sum + weighted gather
    int HC = H * C;
    int nj = C >> 5;  // 32-col chunks per lane
    float denom = 0.f;
    float acc[4] = {0.f, 0.f, 0.f, 0.f};
    for (int k = s; k < e; k++) {
        int src = g_csr[k];
        float ev = g_asrc[src * H + hh] + adn;
        ev = (ev > 0.f) ? ev : NEG_SLOPE * ev;
        float p = __expf(ev - m);
        denom += p;
        const float* hp = hfeat + (size_t)src * HC + hh * C + lane;
        #pragma unroll
        for (int j = 0; j < 4; j++)
            if (j < nj) acc[j] += p * hp[32 * j];
    }

    float inv = 1.f / denom;
    float* op = out + (size_t)n * HC + hh * C + lane;
    const float* bp = bias + hh * C + lane;
    #pragma unroll
    for (int j = 0; j < 4; j++)
        if (j < nj) {
            float v = acc[j] * inv + bp[32 * j];
            op[32 * j] = (v > 0.f) ? v : 0.f;
        }
}

// ---------------- driver: kernel launches only (graph-capturable) ----------------
extern "C" void kernel_launch(void* const* d_in, const int* in_sizes, int n_in,
                              void* d_out, int out_size)
{
    const float* x   = (const float*)d_in[0];
    const int*   ei  = (const int*)d_in[1];     // int32 (JAX default, x64 disabled)
    const float* W1  = (const float*)d_in[2];
    const float* a1s = (const float*)d_in[3];
    const float* a1d = (const float*)d_in[4];
    const float* b1  = (const float*)d_in[5];
    const float* W2  = (const float*)d_in[6];
    const float* a2s = (const float*)d_in[7];
    const float* a2d = (const float*)d_in[8];
    const float* b2  = (const float*)d_in[9];
    const float* W3  = (const float*)d_in[10];
    const float* a3s = (const float*)d_in[11];
    const float* a3d = (const float*)d_in[12];
    const float* b3  = (const float*)d_in[13];
    const float* W4  = (const float*)d_in[14];
    const float* a4s = (const float*)d_in[15];
    const float* a4d = (const float*)d_in[16];
    const float* b4  = (const float*)d_in[17];
    float* out = (float*)d_out;

    const int N = NN;
    const int E0 = in_sizes[1] / 2;

    // ---- CSR (shared by all layers) ----
    k_init_deg<<<cdiv(N, 256), 256>>>(N);
    k_count<<<cdiv(E0, 256), 256>>>(ei, E0, N);
    k_scan<<<1, 1024>>>(N);
    k_place_self<<<cdiv(N, 256), 256>>>(N);
    k_scatter<<<cdiv(E0, 256), 256>>>(ei, E0, N);

    // ---- layer 1: 256 -> (4,128) concat ----
    k_sgemm<true><<<dim3(512 / 64, cdiv(N, 64)), 256>>>(N, 512, 256, x, W1);
    k_alphas<<<N, 128>>>(a1s, a1d, N, 4, 128);
    k_aggregate<false><<<cdiv(N * 4, 8), 256>>>(b1, nullptr, N, 4, 128);

    // ---- layer 2: 512 -> (4,128) concat ----
    k_sgemm<false><<<dim3(512 / 64, cdiv(N, 64)), 256>>>(N, 512, 512, nullptr, W2);
    k_alphas<<<N, 128>>>(a2s, a2d, N, 4, 128);
    k_aggregate<false><<<cdiv(N * 4, 8), 256>>>(b2, nullptr, N, 4, 128);

    // ---- layer 3: 512 -> (4,64) concat ----
    k_sgemm<false><<<dim3(256 / 64, cdiv(N, 64)), 256>>>(N, 256, 512, nullptr, W3);
    k_alphas<<<N, 128>>>(a3s, a3d, N, 4, 64);
    k_aggregate<false><<<cdiv(N * 4, 8), 256>>>(b3, nullptr, N, 4, 64);

    // ---- layer 4: 256 -> (1,64), H=1 so mean == identity ----
    k_sgemm<false><<<dim3(64 / 64, cdiv(N, 64)), 256>>>(N, 64, 256, nullptr, W4);
    k_alphas<<<N, 128>>>(a4s, a4d, N, 1, 64);
    k_aggregate<true><<<cdiv(N * 1, 8), 256>>>(b4, out, N, 1, 64);
}

// round 6
// speedup vs baseline: 1.4216x; 1.4216x over previous
#include <cuda_runtime.h>
#include <cuda_bf16.h>
#include <cstdint>

#define NN 30000
#define MAX_E 520000
#define NEG_SLOPE 0.2f

// ---------------- scratch ----------------
__device__ float g_h[NN * 512];            // GEMM output (fp32)
__device__ float g_feat[NN * 512];         // layer output / next input (fp32)
__device__ __nv_bfloat16 g_ah[NN * 512];   // A split hi
__device__ __nv_bfloat16 g_al[NN * 512];   // A split lo
__device__ __nv_bfloat16 g_bh[512 * 512];  // W^T split hi  [N,K] K-major
__device__ __nv_bfloat16 g_bl[512 * 512];  // W^T split lo
__device__ float g_asrc[NN * 4];
__device__ float g_adst[NN * 4];
__device__ int   g_deg[NN];
__device__ int   g_fill[NN];
__device__ int   g_rowptr[NN + 1];
__device__ int   g_csr[MAX_E];

static inline int cdiv(int a, int b) { return (a + b - 1) / b; }

// ---------------- warp-MMA helpers (sm_80-class, no 'a' features) ----------------
__device__ __forceinline__ uint32_t smem_to_u32(const void* p) {
    uint32_t a;
    asm("{ .reg .u64 t; cvta.to.shared.u64 t, %1; cvt.u32.u64 %0, t; }" : "=r"(a) : "l"(p));
    return a;
}
__device__ __forceinline__ void cp16(uint32_t s, const void* g, bool pred) {
    asm volatile("cp.async.cg.shared.global [%0], [%1], 16, %2;"
                 :: "r"(s), "l"(g), "r"(pred ? 16 : 0));
}
__device__ __forceinline__ void ldm_x4(uint32_t* r, uint32_t a) {
    asm volatile("ldmatrix.sync.aligned.m8n8.x4.shared.b16 {%0,%1,%2,%3}, [%4];"
                 : "=r"(r[0]), "=r"(r[1]), "=r"(r[2]), "=r"(r[3]) : "r"(a));
}
__device__ __forceinline__ void ldm_x2(uint32_t* r, uint32_t a) {
    asm volatile("ldmatrix.sync.aligned.m8n8.x2.shared.b16 {%0,%1}, [%2];"
                 : "=r"(r[0]), "=r"(r[1]) : "r"(a));
}
__device__ __forceinline__ void mma_bf16(float* c, const uint32_t* a, const uint32_t* b) {
    asm volatile("mma.sync.aligned.m16n8k16.row.col.f32.bf16.bf16.f32 "
                 "{%0,%1,%2,%3}, {%4,%5,%6,%7}, {%8,%9}, {%0,%1,%2,%3};"
                 : "+f"(c[0]), "+f"(c[1]), "+f"(c[2]), "+f"(c[3])
                 : "r"(a[0]), "r"(a[1]), "r"(a[2]), "r"(a[3]), "r"(b[0]), "r"(b[1]));
}

// ---------------- CSR build ----------------
__global__ void k_init_deg(int n) {
    int i = blockIdx.x * blockDim.x + threadIdx.x;
    if (i < n) g_deg[i] = 1;
}
__global__ void k_count(const int* __restrict__ ei, int E0, int n) {
    int e = blockIdx.x * blockDim.x + threadIdx.x;
    if (e < E0) {
        int dst = ei[E0 + e];
        if ((unsigned)dst < (unsigned)n) atomicAdd(&g_deg[dst], 1);
    }
}
__global__ void k_scan(int n) {
    __shared__ int sums[1024];
    int t = threadIdx.x;
    int chunk = (n + 1023) / 1024;
    int start = t * chunk; if (start > n) start = n;
    int end = start + chunk; if (end > n) end = n;
    int s = 0;
    for (int i = start; i < end; i++) s += g_deg[i];
    sums[t] = s;
    __syncthreads();
    if (t == 0) {
        int acc = 0;
        for (int i = 0; i < 1024; i++) { int v = sums[i]; sums[i] = acc; acc += v; }
        g_rowptr[n] = acc;
    }
    __syncthreads();
    int acc = sums[t];
    for (int i = start; i < end; i++) { g_rowptr[i] = acc; acc += g_deg[i]; }
}
__global__ void k_place_self(int n) {
    int i = blockIdx.x * blockDim.x + threadIdx.x;
    if (i < n) { g_csr[g_rowptr[i]] = i; g_fill[i] = 1; }
}
__global__ void k_scatter(const int* __restrict__ ei, int E0, int n) {
    int e = blockIdx.x * blockDim.x + threadIdx.x;
    if (e < E0) {
        int src = ei[e];
        int dst = ei[E0 + e];
        if ((unsigned)dst < (unsigned)n && (unsigned)src < (unsigned)n) {
            int pos = atomicAdd(&g_fill[dst], 1);
            g_csr[g_rowptr[dst] + pos] = src;
        }
    }
}

// ---------------- bf16 hi/lo splits ----------------
template <bool A_PARAM>
__global__ void k_split_a(const float* __restrict__ Ap, int total) {
    const float* __restrict__ A = A_PARAM ? Ap : (const float*)g_feat;
    int i = blockIdx.x * blockDim.x + threadIdx.x;
    if (i < total) {
        float a = A[i];
        __nv_bfloat16 hi = __float2bfloat16(a);
        g_ah[i] = hi;
        g_al[i] = __float2bfloat16(a - __bfloat162float(hi));
    }
}

// W[K,N] -> W^T hi/lo [N,K]
__global__ void k_split_w(const float* __restrict__ W, int K, int N) {
    __shared__ float tile[32][33];
    int k0 = blockIdx.y * 32, n0 = blockIdx.x * 32;
    int tx = threadIdx.x, ty = threadIdx.y;  // 32 x 8
    for (int r = ty; r < 32; r += 8) {
        int k = k0 + r, n = n0 + tx;
        tile[r][tx] = (k < K && n < N) ? W[k * N + n] : 0.f;
    }
    __syncthreads();
    for (int r = ty; r < 32; r += 8) {
        int n = n0 + r, k = k0 + tx;
        if (n < N && k < K) {
            float a = tile[tx][r];
            __nv_bfloat16 hi = __float2bfloat16(a);
            g_bh[n * K + k] = hi;
            g_bl[n * K + k] = __float2bfloat16(a - __bfloat162float(hi));
        }
    }
}

// ---------------- split-bf16 tensor-core GEMM: g_h[M,N] = A @ W ----------------
// BM=128, BK=32, BN template. 256 thr, 8 warps. cp.async double-buffered.
// Rows padded to 80B (40 bf16) -> conflict-free ldmatrix.
template <int BN, int WM>
__global__ void __launch_bounds__(256) k_mma(int M, int N, int K) {
    constexpr int WN = 8 / WM;           // warps along n
    constexpr int MI = 128 / WM / 16;    // 16-row frags per warp
    constexpr int ATILE = 128 * 80;      // bytes
    constexpr int BTILE = BN * 80;
    constexpr int STAGE = 2 * ATILE + 2 * BTILE;
    extern __shared__ char smem[];

    int tid = threadIdx.x;
    int wid = tid >> 5, lane = tid & 31;
    int warpM = wid / WN, warpN = wid % WN;
    int rowBase = blockIdx.y * 128, colBase = blockIdx.x * BN;
    int wRow = warpM * (128 / WM), wCol = warpN * 32;

    float acc[MI][4][4];
    #pragma unroll
    for (int mi = 0; mi < MI; mi++)
        #pragma unroll
        for (int ni = 0; ni < 4; ni++)
            #pragma unroll
            for (int j = 0; j < 4; j++) acc[mi][ni][j] = 0.f;

    uint32_t sb = smem_to_u32(smem);

    auto load_stage = [&](int kk, int s) {
        uint32_t base = sb + s * STAGE;
        #pragma unroll
        for (int j = 0; j < 2; j++) {               // A: 512 16B chunks
            int ch = tid + 256 * j;
            int r = ch >> 2, c = ch & 3;
            uint32_t so = r * 80 + c * 16;
            int gr = rowBase + r;
            bool p = gr < M;
            int grc = p ? gr : 0;
            const char* gh = (const char*)(g_ah + (size_t)grc * K + kk) + c * 16;
            const char* gl = (const char*)(g_al + (size_t)grc * K + kk) + c * 16;
            cp16(base + so, gh, p);
            cp16(base + ATILE + so, gl, p);
        }
        #pragma unroll
        for (int j = 0; j < BN / 64; j++) {         // B: BN*4 chunks
            int ch = tid + 256 * j;
            int r = ch >> 2, c = ch & 3;
            uint32_t so = r * 80 + c * 16;
            int gn = colBase + r;
            const char* gh = (const char*)(g_bh + (size_t)gn * K + kk) + c * 16;
            const char* gl = (const char*)(g_bl + (size_t)gn * K + kk) + c * 16;
            cp16(base + 2 * ATILE + so, gh, true);
            cp16(base + 2 * ATILE + BTILE + so, gl, true);
        }
        asm volatile("cp.async.commit_group;" ::: "memory");
    };

    int nstage = K / 32;
    load_stage(0, 0);
    for (int i = 0; i < nstage; i++) {
        if (i + 1 < nstage) {
            load_stage((i + 1) * 32, (i + 1) & 1);
            asm volatile("cp.async.wait_group 1;" ::: "memory");
        } else {
            asm volatile("cp.async.wait_group 0;" ::: "memory");
        }
        __syncthreads();

        uint32_t base = sb + (i & 1) * STAGE;
        #pragma unroll
        for (int ks = 0; ks < 2; ks++) {
            uint32_t ah[MI][4], al[MI][4];
            #pragma unroll
            for (int mi = 0; mi < MI; mi++) {
                int q = lane >> 3, r = lane & 7;
                int row = wRow + mi * 16 + (q & 1) * 8 + r;
                int colb = (ks * 16 + (q >> 1) * 8) * 2;
                uint32_t ad = base + row * 80 + colb;
                ldm_x4(ah[mi], ad);
                ldm_x4(al[mi], ad + ATILE);
            }
            #pragma unroll
            for (int ni = 0; ni < 4; ni++) {
                int r = lane & 7, hf = (lane >> 3) & 1;
                int nrow = wCol + ni * 8 + r;
                int colb = (ks * 16 + hf * 8) * 2;
                uint32_t bd = base + 2 * ATILE + nrow * 80 + colb;
                uint32_t bh[2], bl[2];
                ldm_x2(bh, bd);
                ldm_x2(bl, bd + BTILE);
                #pragma unroll
                for (int mi = 0; mi < MI; mi++) {
                    mma_bf16(acc[mi][ni], ah[mi], bh);   // hi*hi
                    mma_bf16(acc[mi][ni], ah[mi], bl);   // hi*lo
                    mma_bf16(acc[mi][ni], al[mi], bh);   // lo*hi
                }
            }
        }
        __syncthreads();
    }

    // epilogue
    #pragma unroll
    for (int mi = 0; mi < MI; mi++) {
        int row0 = rowBase + wRow + mi * 16 + (lane >> 2);
        #pragma unroll
        for (int ni = 0; ni < 4; ni++) {
            int col = colBase + wCol + ni * 8 + (lane & 3) * 2;
            if (row0 < M)
                *(float2*)(g_h + (size_t)row0 * N + col) =
                    make_float2(acc[mi][ni][0], acc[mi][ni][1]);
            if (row0 + 8 < M)
                *(float2*)(g_h + (size_t)(row0 + 8) * N + col) =
                    make_float2(acc[mi][ni][2], acc[mi][ni][3]);
        }
    }
}

// ---------------- per-node attention logits ----------------
__global__ void k_alphas(const float* __restrict__ a_s, const float* __restrict__ a_d,
                         int N, int H, int C) {
    int n = blockIdx.x;
    int w = threadIdx.x >> 5;
    int lane = threadIdx.x & 31;
    if (w >= H) return;
    const float* hp = g_h + (size_t)n * H * C + w * C;
    float s1 = 0.f, s2 = 0.f;
    for (int c = lane; c < C; c += 32) {
        float v = hp[c];
        s1 += v * a_s[w * C + c];
        s2 += v * a_d[w * C + c];
    }
    #pragma unroll
    for (int o = 16; o > 0; o >>= 1) {
        s1 += __shfl_down_sync(0xffffffffu, s1, o);
        s2 += __shfl_down_sync(0xffffffffu, s2, o);
    }
    if (lane == 0) {
        g_asrc[n * H + w] = s1;
        g_adst[n * H + w] = s2;
    }
}

// ---------------- fused softmax + aggregate + bias + relu ----------------
template <bool TO_OUT>
__global__ void __launch_bounds__(256) k_aggregate(
    const float* __restrict__ bias, float* __restrict__ outp, int N, int H, int C) {
    float* __restrict__ out = TO_OUT ? outp : (float*)g_feat;
    const float* __restrict__ hfeat = g_h;

    int unit = (blockIdx.x * blockDim.x + threadIdx.x) >> 5;
    int lane = threadIdx.x & 31;
    if (unit >= N * H) return;
    int n = unit / H;
    int hh = unit - n * H;

    int s = g_rowptr[n];
    int e = g_rowptr[n + 1];
    float adn = g_adst[n * H + hh];

    float m = -1e30f;
    for (int k = s; k < e; k++) {
        int src = g_csr[k];
        float ev = g_asrc[src * H + hh] + adn;
        ev = (ev > 0.f) ? ev : NEG_SLOPE * ev;
        m = fmaxf(m, ev);
    }

    int HC = H * C;
    int nj = C >> 5;
    float denom = 0.f;
    float acc[4] = {0.f, 0.f, 0.f, 0.f};
    for (int k = s; k < e; k++) {
        int src = g_csr[k];
        float ev = g_asrc[src * H + hh] + adn;
        ev = (ev > 0.f) ? ev : NEG_SLOPE * ev;
        float p = __expf(ev - m);
        denom += p;
        const float* hp = hfeat + (size_t)src * HC + hh * C + lane;
        #pragma unroll
        for (int j = 0; j < 4; j++)
            if (j < nj) acc[j] += p * hp[32 * j];
    }

    float inv = 1.f / denom;
    float* op = out + (size_t)n * HC + hh * C + lane;
    const float* bp = bias + hh * C + lane;
    #pragma unroll
    for (int j = 0; j < 4; j++)
        if (j < nj) {
            float v = acc[j] * inv + bp[32 * j];
            op[32 * j] = (v > 0.f) ? v : 0.f;
        }
}

// ---------------- driver ----------------
extern "C" void kernel_launch(void* const* d_in, const int* in_sizes, int n_in,
                              void* d_out, int out_size) {
    const float* x   = (const float*)d_in[0];
    const int*   ei  = (const int*)d_in[1];
    const float* W1  = (const float*)d_in[2];
    const float* a1s = (const float*)d_in[3];
    const float* a1d = (const float*)d_in[4];
    const float* b1  = (const float*)d_in[5];
    const float* W2  = (const float*)d_in[6];
    const float* a2s = (const float*)d_in[7];
    const float* a2d = (const float*)d_in[8];
    const float* b2  = (const float*)d_in[9];
    const float* W3  = (const float*)d_in[10];
    const float* a3s = (const float*)d_in[11];
    const float* a3d = (const float*)d_in[12];
    const float* b3  = (const float*)d_in[13];
    const float* W4  = (const float*)d_in[14];
    const float* a4s = (const float*)d_in[15];
    const float* a4d = (const float*)d_in[16];
    const float* b4  = (const float*)d_in[17];
    float* out = (float*)d_out;

    const int N = NN;
    const int E0 = in_sizes[1] / 2;
    const int MB = cdiv(N, 128);  // 235

    const int SMEM128 = 2 * (2 * 128 * 80 + 2 * 128 * 80);  // 81920
    const int SMEM64  = 2 * (2 * 128 * 80 + 2 * 64 * 80);   // 61440
    cudaFuncSetAttribute(k_mma<128, 2>, cudaFuncAttributeMaxDynamicSharedMemorySize, SMEM128);
    cudaFuncSetAttribute(k_mma<64, 4>,  cudaFuncAttributeMaxDynamicSharedMemorySize, SMEM64);

    // ---- CSR (shared by all layers) ----
    k_init_deg<<<cdiv(N, 256), 256>>>(N);
    k_count<<<cdiv(E0, 256), 256>>>(ei, E0, N);
    k_scan<<<1, 1024>>>(N);
    k_place_self<<<cdiv(N, 256), 256>>>(N);
    k_scatter<<<cdiv(E0, 256), 256>>>(ei, E0, N);

    // ---- layer 1: K=256 -> N=512 (H=4,C=128) ----
    k_split_a<true><<<cdiv(N * 256, 256), 256>>>(x, N * 256);
    k_split_w<<<dim3(cdiv(512, 32), cdiv(256, 32)), dim3(32, 8)>>>(W1, 256, 512);
    k_mma<128, 2><<<dim3(4, MB), 256, SMEM128>>>(N, 512, 256);
    k_alphas<<<N, 128>>>(a1s, a1d, N, 4, 128);
    k_aggregate<false><<<cdiv(N * 4, 8), 256>>>(b1, nullptr, N, 4, 128);

    // ---- layer 2: K=512 -> N=512 (H=4,C=128) ----
    k_split_a<false><<<cdiv(N * 512, 256), 256>>>(nullptr, N * 512);
    k_split_w<<<dim3(cdiv(512, 32), cdiv(512, 32)), dim3(32, 8)>>>(W2, 512, 512);
    k_mma<128, 2><<<dim3(4, MB), 256, SMEM128>>>(N, 512, 512);
    k_alphas<<<N, 128>>>(a2s, a2d, N, 4, 128);
    k_aggregate<false><<<cdiv(N * 4, 8), 256>>>(b2, nullptr, N, 4, 128);

    // ---- layer 3: K=512 -> N=256 (H=4,C=64) ----
    k_split_a<false><<<cdiv(N * 512, 256), 256>>>(nullptr, N * 512);
    k_split_w<<<dim3(cdiv(256, 32), cdiv(512, 32)), dim3(32, 8)>>>(W3, 512, 256);
    k_mma<128, 2><<<dim3(2, MB), 256, SMEM128>>>(N, 256, 512);
    k_alphas<<<N, 128>>>(a3s, a3d, N, 4, 64);
    k_aggregate<false><<<cdiv(N * 4, 8), 256>>>(b3, nullptr, N, 4, 64);

    // ---- layer 4: K=256 -> N=64 (H=1,C=64, mean==identity) ----
    k_split_a<false><<<cdiv(N * 256, 256), 256>>>(nullptr, N * 256);
    k_split_w<<<dim3(cdiv(64, 32), cdiv(256, 32)), dim3(32, 8)>>>(W4, 256, 64);
    k_mma<64, 4><<<dim3(1, MB), 256, SMEM64>>>(N, 64, 256);
    k_alphas<<<N, 128>>>(a4s, a4d, N, 1, 64);
    k_aggregate<true><<<cdiv(N * 1, 8), 256>>>(b4, out, N, 1, 64);
}

// round 8
// speedup vs baseline: 1.8343x; 1.2903x over previous
#include <cuda_runtime.h>
#include <cuda_bf16.h>
#include <cstdint>

#define NN 30000
#define MAX_E 520000
#define NEG_SLOPE 0.2f

// ---------------- scratch ----------------
__device__ float g_h[NN * 512];            // GEMM output (fp32)
__device__ __nv_bfloat16 g_ah[NN * 512];   // features split hi (GEMM A input)
__device__ __nv_bfloat16 g_al[NN * 512];   // features split lo
__device__ __nv_bfloat16 g_bh[512 * 512];  // W^T split hi  [N,K] K-major
__device__ __nv_bfloat16 g_bl[512 * 512];  // W^T split lo
__device__ float g_asrc[NN * 4];
__device__ float g_adst[NN * 4];
__device__ int   g_deg[NN];
__device__ int   g_fill[NN];
__device__ int   g_rowptr[NN + 1];
__device__ int   g_csr[MAX_E];

static inline int cdiv(int a, int b) { return (a + b - 1) / b; }

// ---------------- warp-MMA helpers (sm_80-class, no 'a' features) ----------------
__device__ __forceinline__ uint32_t smem_to_u32(const void* p) {
    uint32_t a;
    asm("{ .reg .u64 t; cvta.to.shared.u64 t, %1; cvt.u32.u64 %0, t; }" : "=r"(a) : "l"(p));
    return a;
}
__device__ __forceinline__ void cp16(uint32_t s, const void* g, bool pred) {
    asm volatile("cp.async.cg.shared.global [%0], [%1], 16, %2;"
                 :: "r"(s), "l"(g), "r"(pred ? 16 : 0));
}
__device__ __forceinline__ void ldm_x4(uint32_t* r, uint32_t a) {
    asm volatile("ldmatrix.sync.aligned.m8n8.x4.shared.b16 {%0,%1,%2,%3}, [%4];"
                 : "=r"(r[0]), "=r"(r[1]), "=r"(r[2]), "=r"(r[3]) : "r"(a));
}
__device__ __forceinline__ void ldm_x2(uint32_t* r, uint32_t a) {
    asm volatile("ldmatrix.sync.aligned.m8n8.x2.shared.b16 {%0,%1}, [%2];"
                 : "=r"(r[0]), "=r"(r[1]) : "r"(a));
}
__device__ __forceinline__ void mma_bf16(float* c, const uint32_t* a, const uint32_t* b) {
    asm volatile("mma.sync.aligned.m16n8k16.row.col.f32.bf16.bf16.f32 "
                 "{%0,%1,%2,%3}, {%4,%5,%6,%7}, {%8,%9}, {%0,%1,%2,%3};"
                 : "+f"(c[0]), "+f"(c[1]), "+f"(c[2]), "+f"(c[3])
                 : "r"(a[0]), "r"(a[1]), "r"(a[2]), "r"(a[3]), "r"(b[0]), "r"(b[1]));
}

// ---------------- CSR build ----------------
__global__ void k_init_deg(int n) {
    int i = blockIdx.x * blockDim.x + threadIdx.x;
    if (i < n) g_deg[i] = 1;
}
__global__ void k_count(const int* __restrict__ ei, int E0, int n) {
    int e = blockIdx.x * blockDim.x + threadIdx.x;
    if (e < E0) {
        int dst = ei[E0 + e];
        if ((unsigned)dst < (unsigned)n) atomicAdd(&g_deg[dst], 1);
    }
}
__global__ void k_scan(int n) {
    __shared__ int sums[1024];
    int t = threadIdx.x;
    int chunk = (n + 1023) / 1024;
    int start = t * chunk; if (start > n) start = n;
    int end = start + chunk; if (end > n) end = n;
    int s = 0;
    for (int i = start; i < end; i++) s += g_deg[i];
    sums[t] = s;
    __syncthreads();
    if (t == 0) {
        int acc = 0;
        for (int i = 0; i < 1024; i++) { int v = sums[i]; sums[i] = acc; acc += v; }
        g_rowptr[n] = acc;
    }
    __syncthreads();
    int acc = sums[t];
    for (int i = start; i < end; i++) { g_rowptr[i] = acc; acc += g_deg[i]; }
}
__global__ void k_place_self(int n) {
    int i = blockIdx.x * blockDim.x + threadIdx.x;
    if (i < n) { g_csr[g_rowptr[i]] = i; g_fill[i] = 1; }
}
__global__ void k_scatter(const int* __restrict__ ei, int E0, int n) {
    int e = blockIdx.x * blockDim.x + threadIdx.x;
    if (e < E0) {
        int src = ei[e];
        int dst = ei[E0 + e];
        if ((unsigned)dst < (unsigned)n && (unsigned)src < (unsigned)n) {
            int pos = atomicAdd(&g_fill[dst], 1);
            g_csr[g_rowptr[dst] + pos] = src;
        }
    }
}

// ---------------- bf16 hi/lo split of layer-1 input ----------------
__global__ void k_split_a(const float* __restrict__ A, int total) {
    int i = blockIdx.x * blockDim.x + threadIdx.x;
    if (i < total) {
        float a = A[i];
        __nv_bfloat16 hi = __float2bfloat16(a);
        g_ah[i] = hi;
        g_al[i] = __float2bfloat16(a - __bfloat162float(hi));
    }
}

// W[K,N] -> W^T hi/lo [N,K]
__global__ void k_split_w(const float* __restrict__ W, int K, int N) {
    __shared__ float tile[32][33];
    int k0 = blockIdx.y * 32, n0 = blockIdx.x * 32;
    int tx = threadIdx.x, ty = threadIdx.y;  // 32 x 8
    for (int r = ty; r < 32; r += 8) {
        int k = k0 + r, n = n0 + tx;
        tile[r][tx] = (k < K && n < N) ? W[k * N + n] : 0.f;
    }
    __syncthreads();
    for (int r = ty; r < 32; r += 8) {
        int n = n0 + r, k = k0 + tx;
        if (n < N && k < K) {
            float a = tile[tx][r];
            __nv_bfloat16 hi = __float2bfloat16(a);
            g_bh[n * K + k] = hi;
            g_bl[n * K + k] = __float2bfloat16(a - __bfloat162float(hi));
        }
    }
}

// ---------------- split-bf16 tensor-core GEMM: g_h[M,N] = A @ W ----------------
// BM=128, BK=32, BN template. 256 thr, 8 warps, 2 CTAs/SM target.
template <int BN, int WM>
__global__ void __launch_bounds__(256, 2) k_mma(int M, int N, int K) {
    constexpr int WN = 8 / WM;
    constexpr int MI = 128 / WM / 16;
    constexpr int ATILE = 128 * 80;
    constexpr int BTILE = BN * 80;
    constexpr int STAGE = 2 * ATILE + 2 * BTILE;
    extern __shared__ char smem[];

    int tid = threadIdx.x;
    int wid = tid >> 5, lane = tid & 31;
    int warpM = wid / WN, warpN = wid % WN;
    int rowBase = blockIdx.y * 128, colBase = blockIdx.x * BN;
    int wRow = warpM * (128 / WM), wCol = warpN * 32;

    float acc[MI][4][4];
    #pragma unroll
    for (int mi = 0; mi < MI; mi++)
        #pragma unroll
        for (int ni = 0; ni < 4; ni++)
            #pragma unroll
            for (int j = 0; j < 4; j++) acc[mi][ni][j] = 0.f;

    uint32_t sb = smem_to_u32(smem);

    auto load_stage = [&](int kk, int s) {
        uint32_t base = sb + s * STAGE;
        #pragma unroll
        for (int j = 0; j < 2; j++) {
            int ch = tid + 256 * j;
            int r = ch >> 2, c = ch & 3;
            uint32_t so = r * 80 + c * 16;
            int gr = rowBase + r;
            bool p = gr < M;
            int grc = p ? gr : 0;
            const char* gh = (const char*)(g_ah + (size_t)grc * K + kk) + c * 16;
            const char* gl = (const char*)(g_al + (size_t)grc * K + kk) + c * 16;
            cp16(base + so, gh, p);
            cp16(base + ATILE + so, gl, p);
        }
        #pragma unroll
        for (int j = 0; j < BN / 64; j++) {
            int ch = tid + 256 * j;
            int r = ch >> 2, c = ch & 3;
            uint32_t so = r * 80 + c * 16;
            int gn = colBase + r;
            const char* gh = (const char*)(g_bh + (size_t)gn * K + kk) + c * 16;
            const char* gl = (const char*)(g_bl + (size_t)gn * K + kk) + c * 16;
            cp16(base + 2 * ATILE + so, gh, true);
            cp16(base + 2 * ATILE + BTILE + so, gl, true);
        }
        asm volatile("cp.async.commit_group;" ::: "memory");
    };

    int nstage = K / 32;
    load_stage(0, 0);
    for (int i = 0; i < nstage; i++) {
        if (i + 1 < nstage) {
            load_stage((i + 1) * 32, (i + 1) & 1);
            asm volatile("cp.async.wait_group 1;" ::: "memory");
        } else {
            asm volatile("cp.async.wait_group 0;" ::: "memory");
        }
        __syncthreads();

        uint32_t base = sb + (i & 1) * STAGE;
        #pragma unroll
        for (int ks = 0; ks < 2; ks++) {
            uint32_t ah[MI][4], al[MI][4];
            #pragma unroll
            for (int mi = 0; mi < MI; mi++) {
                int q = lane >> 3, r = lane & 7;
                int row = wRow + mi * 16 + (q & 1) * 8 + r;
                int colb = (ks * 16 + (q >> 1) * 8) * 2;
                uint32_t ad = base + row * 80 + colb;
                ldm_x4(ah[mi], ad);
                ldm_x4(al[mi], ad + ATILE);
            }
            #pragma unroll
            for (int ni = 0; ni < 4; ni++) {
                int r = lane & 7, hf = (lane >> 3) & 1;
                int nrow = wCol + ni * 8 + r;
                int colb = (ks * 16 + hf * 8) * 2;
                uint32_t bd = base + 2 * ATILE + nrow * 80 + colb;
                uint32_t bh[2], bl[2];
                ldm_x2(bh, bd);
                ldm_x2(bl, bd + BTILE);
                #pragma unroll
                for (int mi = 0; mi < MI; mi++) {
                    mma_bf16(acc[mi][ni], ah[mi], bh);
                    mma_bf16(acc[mi][ni], ah[mi], bl);
                    mma_bf16(acc[mi][ni], al[mi], bh);
                }
            }
        }
        __syncthreads();
    }

    #pragma unroll
    for (int mi = 0; mi < MI; mi++) {
        int row0 = rowBase + wRow + mi * 16 + (lane >> 2);
        #pragma unroll
        for (int ni = 0; ni < 4; ni++) {
            int col = colBase + wCol + ni * 8 + (lane & 3) * 2;
            if (row0 < M)
                *(float2*)(g_h + (size_t)row0 * N + col) =
                    make_float2(acc[mi][ni][0], acc[mi][ni][1]);
            if (row0 + 8 < M)
                *(float2*)(g_h + (size_t)(row0 + 8) * N + col) =
                    make_float2(acc[mi][ni][2], acc[mi][ni][3]);
        }
    }
}

// ---------------- per-(node,head) attention logits, warp-per-unit, float4 ----------------
template <int C>
__global__ void k_alphas(const float* __restrict__ a_s, const float* __restrict__ a_d,
                         int N, int H) {
    int unit = (blockIdx.x * blockDim.x + threadIdx.x) >> 5;
    int lane = threadIdx.x & 31;
    if (unit >= N * H) return;
    int n = unit / H;
    int hh = unit - n * H;
    float s1 = 0.f, s2 = 0.f;
    if (lane < C / 4) {
        const float4* hp = (const float4*)(g_h + (size_t)n * H * C + hh * C);
        const float4* sp = (const float4*)(a_s + hh * C);
        const float4* dp = (const float4*)(a_d + hh * C);
        float4 v = hp[lane], a = sp[lane], b = dp[lane];
        s1 = v.x * a.x + v.y * a.y + v.z * a.z + v.w * a.w;
        s2 = v.x * b.x + v.y * b.y + v.z * b.z + v.w * b.w;
    }
    #pragma unroll
    for (int o = 16; o > 0; o >>= 1) {
        s1 += __shfl_xor_sync(0xffffffffu, s1, o);
        s2 += __shfl_xor_sync(0xffffffffu, s2, o);
    }
    if (lane == 0) {
        g_asrc[n * H + hh] = s1;
        g_adst[n * H + hh] = s2;
    }
}

// ---------------- fused softmax + aggregate + bias + relu (+ bf16 split) ----------------
// group of G = C/4 lanes per (node,head); float4 gather.
template <int C, bool TO_OUT>
__global__ void __launch_bounds__(256) k_aggregate(
    const float* __restrict__ bias, float* __restrict__ outp, int N, int H) {
    constexpr int G = C / 4;                 // 32 (C=128) or 16 (C=64)
    int unit = (blockIdx.x * blockDim.x + threadIdx.x) / G;
    int l = threadIdx.x & (G - 1);
    if (unit >= N * H) return;
    int n = unit / H;
    int hh = unit - n * H;
    int HC = H * C;

    int s = g_rowptr[n];
    int e = g_rowptr[n + 1];
    float adn = g_adst[n * H + hh];

    // pass 1: lane-parallel max
    float m = -1e30f;
    for (int k = s + l; k < e; k += G) {
        int src = g_csr[k];
        float ev = g_asrc[src * H + hh] + adn;
        ev = (ev > 0.f) ? ev : NEG_SLOPE * ev;
        m = fmaxf(m, ev);
    }
    #pragma unroll
    for (int o = G / 2; o > 0; o >>= 1)
        m = fmaxf(m, __shfl_xor_sync(0xffffffffu, m, o, G));

    // pass 2: exp-sum + float4 weighted gather
    float denom = 0.f;
    float4 acc = make_float4(0.f, 0.f, 0.f, 0.f);
    for (int k = s; k < e; k++) {
        int src = g_csr[k];
        float ev = g_asrc[src * H + hh] + adn;
        ev = (ev > 0.f) ? ev : NEG_SLOPE * ev;
        float p = __expf(ev - m);
        denom += p;
        const float4* hp = (const float4*)(g_h + (size_t)src * HC + hh * C);
        float4 v = hp[l];
        acc.x += p * v.x; acc.y += p * v.y; acc.z += p * v.z; acc.w += p * v.w;
    }

    float inv = 1.f / denom;
    const float4* bp = (const float4*)(bias + hh * C);
    float4 bv = bp[l];
    float4 r;
    r.x = fmaxf(acc.x * inv + bv.x, 0.f);
    r.y = fmaxf(acc.y * inv + bv.y, 0.f);
    r.z = fmaxf(acc.z * inv + bv.z, 0.f);
    r.w = fmaxf(acc.w * inv + bv.w, 0.f);

    size_t base = (size_t)n * HC + hh * C + l * 4;
    if (TO_OUT) {
        *(float4*)(outp + base) = r;
    } else {
        // write bf16 hi/lo directly for the next layer's GEMM
        __nv_bfloat16 hx = __float2bfloat16(r.x), hy = __float2bfloat16(r.y);
        __nv_bfloat16 hz = __float2bfloat16(r.z), hw = __float2bfloat16(r.w);
        __nv_bfloat162* ph = (__nv_bfloat162*)(g_ah + base);
        ph[0] = __nv_bfloat162(hx, hy);
        ph[1] = __nv_bfloat162(hz, hw);
        __nv_bfloat162* pl = (__nv_bfloat162*)(g_al + base);
        pl[0] = __nv_bfloat162(__float2bfloat16(r.x - __bfloat162float(hx)),
                               __float2bfloat16(r.y - __bfloat162float(hy)));
        pl[1] = __nv_bfloat162(__float2bfloat16(r.z - __bfloat162float(hz)),
                               __float2bfloat16(r.w - __bfloat162float(hw)));
    }
}

// ---------------- driver ----------------
extern "C" void kernel_launch(void* const* d_in, const int* in_sizes, int n_in,
                              void* d_out, int out_size) {
    const float* x   = (const float*)d_in[0];
    const int*   ei  = (const int*)d_in[1];
    const float* W1  = (const float*)d_in[2];
    const float* a1s = (const float*)d_in[3];
    const float* a1d = (const float*)d_in[4];
    const float* b1  = (const float*)d_in[5];
    const float* W2  = (const float*)d_in[6];
    const float* a2s = (const float*)d_in[7];
    const float* a2d = (const float*)d_in[8];
    const float* b2  = (const float*)d_in[9];
    const float* W3  = (const float*)d_in[10];
    const float* a3s = (const float*)d_in[11];
    const float* a3d = (const float*)d_in[12];
    const float* b3  = (const float*)d_in[13];
    const float* W4  = (const float*)d_in[14];
    const float* a4s = (const float*)d_in[15];
    const float* a4d = (const float*)d_in[16];
    const float* b4  = (const float*)d_in[17];
    float* out = (float*)d_out;

    const int N = NN;
    const int E0 = in_sizes[1] / 2;
    const int MB = cdiv(N, 128);

    const int SMEM128 = 2 * (2 * 128 * 80 + 2 * 128 * 80);  // 81920
    const int SMEM64  = 2 * (2 * 128 * 80 + 2 * 64 * 80);   // 61440
    cudaFuncSetAttribute(k_mma<128, 2>, cudaFuncAttributeMaxDynamicSharedMemorySize, SMEM128);
    cudaFuncSetAttribute(k_mma<64, 4>,  cudaFuncAttributeMaxDynamicSharedMemorySize, SMEM64);

    // ---- CSR (shared by all layers) ----
    k_init_deg<<<cdiv(N, 256), 256>>>(N);
    k_count<<<cdiv(E0, 256), 256>>>(ei, E0, N);
    k_scan<<<1, 1024>>>(N);
    k_place_self<<<cdiv(N, 256), 256>>>(N);
    k_scatter<<<cdiv(E0, 256), 256>>>(ei, E0, N);

    // ---- layer 1: K=256 -> N=512 (H=4,C=128) ----
    k_split_a<<<cdiv(N * 256, 256), 256>>>(x, N * 256);
    k_split_w<<<dim3(cdiv(512, 32), cdiv(256, 32)), dim3(32, 8)>>>(W1, 256, 512);
    k_mma<128, 2><<<dim3(4, MB), 256, SMEM128>>>(N, 512, 256);
    k_alphas<128><<<cdiv(N * 4, 8), 256>>>(a1s, a1d, N, 4);
    k_aggregate<128, false><<<cdiv(N * 4, 8), 256>>>(b1, nullptr, N, 4);

    // ---- layer 2: K=512 -> N=512 (H=4,C=128) ----
    k_split_w<<<dim3(cdiv(512, 32), cdiv(512, 32)), dim3(32, 8)>>>(W2, 512, 512);
    k_mma<128, 2><<<dim3(4, MB), 256, SMEM128>>>(N, 512, 512);
    k_alphas<128><<<cdiv(N * 4, 8), 256>>>(a2s, a2d, N, 4);
    k_aggregate<128, false><<<cdiv(N * 4, 8), 256>>>(b2, nullptr, N, 4);

    // ---- layer 3: K=512 -> N=256 (H=4,C=64) ----
    k_split_w<<<dim3(cdiv(256, 32), cdiv(512, 32)), dim3(32, 8)>>>(W3, 512, 256);
    k_mma<128, 2><<<dim3(2, MB), 256, SMEM128>>>(N, 256, 512);
    k_alphas<64><<<cdiv(N * 4, 8), 256>>>(a3s, a3d, N, 4);
    k_aggregate<64, false><<<cdiv(N * 4, 16), 256>>>(b3, nullptr, N, 4);

    // ---- layer 4: K=256 -> N=64 (H=1,C=64, mean==identity) ----
    k_split_w<<<dim3(cdiv(64, 32), cdiv(256, 32)), dim3(32, 8)>>>(W4, 256, 64);
    k_mma<64, 4><<<dim3(1, MB), 256, SMEM64>>>(N, 64, 256);
    k_alphas<64><<<cdiv(N * 1, 8), 256>>>(a4s, a4d, N, 1);
    k_aggregate<64, true><<<cdiv(N * 1, 16), 256>>>(b4, out, N, 1);
}

// round 9
// speedup vs baseline: 1.9333x; 1.0539x over previous
#include <cuda_runtime.h>
#include <cuda_bf16.h>
#include <cstdint>

#define NN 30000
#define MAX_E 520000
#define NEG_SLOPE 0.2f

// ---------------- scratch ----------------
__device__ float g_h[NN * 512];            // GEMM output (fp32)
__device__ __nv_bfloat16 g_ah[NN * 512];   // features split hi (GEMM A input)
__device__ __nv_bfloat16 g_al[NN * 512];   // features split lo
__device__ __nv_bfloat16 g_bh[540672];     // all layers' W^T hi  [N,K] K-major
__device__ __nv_bfloat16 g_bl[540672];     // all layers' W^T lo
__device__ float g_asrc[NN * 4];
__device__ float g_adst[NN * 4];
__device__ int   g_deg[NN];
__device__ int   g_fill[NN];
__device__ int   g_rowptr[NN + 1];
__device__ int   g_csr[MAX_E];

// weight buffer offsets: L1 512x256, L2 512x512, L3 256x512, L4 64x256
#define WOF1 0
#define WOF2 131072
#define WOF3 393216
#define WOF4 524288

static inline int cdiv(int a, int b) { return (a + b - 1) / b; }

// ---------------- warp-MMA helpers (sm_80-class, no 'a' features) ----------------
__device__ __forceinline__ uint32_t smem_to_u32(const void* p) {
    uint32_t a;
    asm("{ .reg .u64 t; cvta.to.shared.u64 t, %1; cvt.u32.u64 %0, t; }" : "=r"(a) : "l"(p));
    return a;
}
__device__ __forceinline__ void cp16(uint32_t s, const void* g, bool pred) {
    asm volatile("cp.async.cg.shared.global [%0], [%1], 16, %2;"
                 :: "r"(s), "l"(g), "r"(pred ? 16 : 0));
}
__device__ __forceinline__ void ldm_x4(uint32_t* r, uint32_t a) {
    asm volatile("ldmatrix.sync.aligned.m8n8.x4.shared.b16 {%0,%1,%2,%3}, [%4];"
                 : "=r"(r[0]), "=r"(r[1]), "=r"(r[2]), "=r"(r[3]) : "r"(a));
}
__device__ __forceinline__ void ldm_x2(uint32_t* r, uint32_t a) {
    asm volatile("ldmatrix.sync.aligned.m8n8.x2.shared.b16 {%0,%1}, [%2];"
                 : "=r"(r[0]), "=r"(r[1]) : "r"(a));
}
__device__ __forceinline__ void mma_bf16(float* c, const uint32_t* a, const uint32_t* b) {
    asm volatile("mma.sync.aligned.m16n8k16.row.col.f32.bf16.bf16.f32 "
                 "{%0,%1,%2,%3}, {%4,%5,%6,%7}, {%8,%9}, {%0,%1,%2,%3};"
                 : "+f"(c[0]), "+f"(c[1]), "+f"(c[2]), "+f"(c[3])
                 : "r"(a[0]), "r"(a[1]), "r"(a[2]), "r"(a[3]), "r"(b[0]), "r"(b[1]));
}

// ---------------- CSR build ----------------
__global__ void k_init_deg(int n) {
    int i = blockIdx.x * blockDim.x + threadIdx.x;
    if (i < n) g_deg[i] = 1;
}
__global__ void k_count(const int* __restrict__ ei, int E0, int n) {
    int e = blockIdx.x * blockDim.x + threadIdx.x;
    if (e < E0) {
        int dst = ei[E0 + e];
        if ((unsigned)dst < (unsigned)n) atomicAdd(&g_deg[dst], 1);
    }
}
__global__ void k_scan(int n) {
    __shared__ int sums[1024];
    int t = threadIdx.x;
    int chunk = (n + 1023) / 1024;
    int start = t * chunk; if (start > n) start = n;
    int end = start + chunk; if (end > n) end = n;
    int s = 0;
    for (int i = start; i < end; i++) s += g_deg[i];
    sums[t] = s;
    __syncthreads();
    if (t == 0) {
        int acc = 0;
        for (int i = 0; i < 1024; i++) { int v = sums[i]; sums[i] = acc; acc += v; }
        g_rowptr[n] = acc;
    }
    __syncthreads();
    int acc = sums[t];
    for (int i = start; i < end; i++) { g_rowptr[i] = acc; acc += g_deg[i]; }
}
__global__ void k_place_self(int n) {
    int i = blockIdx.x * blockDim.x + threadIdx.x;
    if (i < n) { g_csr[g_rowptr[i]] = i; g_fill[i] = 1; }
}
__global__ void k_scatter(const int* __restrict__ ei, int E0, int n) {
    int e = blockIdx.x * blockDim.x + threadIdx.x;
    if (e < E0) {
        int src = ei[e];
        int dst = ei[E0 + e];
        if ((unsigned)dst < (unsigned)n && (unsigned)src < (unsigned)n) {
            int pos = atomicAdd(&g_fill[dst], 1);
            g_csr[g_rowptr[dst] + pos] = src;
        }
    }
}

// ---------------- bf16 hi/lo split of layer-1 input ----------------
__global__ void k_split_a(const float* __restrict__ A, int total) {
    int i = blockIdx.x * blockDim.x + threadIdx.x;
    if (i < total) {
        float a = A[i];
        __nv_bfloat16 hi = __float2bfloat16(a);
        g_ah[i] = hi;
        g_al[i] = __float2bfloat16(a - __bfloat162float(hi));
    }
}

// W[K,N] -> W^T hi/lo [N,K] at buffer offset
__global__ void k_split_w(const float* __restrict__ W, int K, int N, int off) {
    __shared__ float tile[32][33];
    int k0 = blockIdx.y * 32, n0 = blockIdx.x * 32;
    int tx = threadIdx.x, ty = threadIdx.y;  // 32 x 8
    for (int r = ty; r < 32; r += 8) {
        int k = k0 + r, n = n0 + tx;
        tile[r][tx] = (k < K && n < N) ? W[k * N + n] : 0.f;
    }
    __syncthreads();
    for (int r = ty; r < 32; r += 8) {
        int n = n0 + r, k = k0 + tx;
        if (n < N && k < K) {
            float a = tile[tx][r];
            __nv_bfloat16 hi = __float2bfloat16(a);
            g_bh[off + n * K + k] = hi;
            g_bl[off + n * K + k] = __float2bfloat16(a - __bfloat162float(hi));
        }
    }
}

// ---------------- split-bf16 tensor-core GEMM: g_h[M,N] = A @ W ----------------
// BM=128, BK=32, BN template. 256 thr, 8 warps, 2 CTAs/SM.
template <int BN, int WM>
__global__ void __launch_bounds__(256, 2) k_mma(int M, int N, int K, int boff) {
    constexpr int WN = 8 / WM;
    constexpr int MI = 128 / WM / 16;
    constexpr int ATILE = 128 * 80;
    constexpr int BTILE = BN * 80;
    constexpr int STAGE = 2 * ATILE + 2 * BTILE;
    extern __shared__ char smem[];

    int tid = threadIdx.x;
    int wid = tid >> 5, lane = tid & 31;
    int warpM = wid / WN, warpN = wid % WN;
    int rowBase = blockIdx.y * 128, colBase = blockIdx.x * BN;
    int wRow = warpM * (128 / WM), wCol = warpN * 32;

    const __nv_bfloat16* __restrict__ Bh = g_bh + boff;
    const __nv_bfloat16* __restrict__ Bl = g_bl + boff;

    float acc[MI][4][4];
    #pragma unroll
    for (int mi = 0; mi < MI; mi++)
        #pragma unroll
        for (int ni = 0; ni < 4; ni++)
            #pragma unroll
            for (int j = 0; j < 4; j++) acc[mi][ni][j] = 0.f;

    uint32_t sb = smem_to_u32(smem);

    auto load_stage = [&](int kk, int s) {
        uint32_t base = sb + s * STAGE;
        #pragma unroll
        for (int j = 0; j < 2; j++) {
            int ch = tid + 256 * j;
            int r = ch >> 2, c = ch & 3;
            uint32_t so = r * 80 + c * 16;
            int gr = rowBase + r;
            bool p = gr < M;
            int grc = p ? gr : 0;
            const char* gh = (const char*)(g_ah + (size_t)grc * K + kk) + c * 16;
            const char* gl = (const char*)(g_al + (size_t)grc * K + kk) + c * 16;
            cp16(base + so, gh, p);
            cp16(base + ATILE + so, gl, p);
        }
        #pragma unroll
        for (int j = 0; j < BN / 64; j++) {
            int ch = tid + 256 * j;
            int r = ch >> 2, c = ch & 3;
            uint32_t so = r * 80 + c * 16;
            int gn = colBase + r;
            const char* gh = (const char*)(Bh + (size_t)gn * K + kk) + c * 16;
            const char* gl = (const char*)(Bl + (size_t)gn * K + kk) + c * 16;
            cp16(base + 2 * ATILE + so, gh, true);
            cp16(base + 2 * ATILE + BTILE + so, gl, true);
        }
        asm volatile("cp.async.commit_group;" ::: "memory");
    };

    int nstage = K / 32;
    load_stage(0, 0);
    for (int i = 0; i < nstage; i++) {
        if (i + 1 < nstage) {
            load_stage((i + 1) * 32, (i + 1) & 1);
            asm volatile("cp.async.wait_group 1;" ::: "memory");
        } else {
            asm volatile("cp.async.wait_group 0;" ::: "memory");
        }
        __syncthreads();

        uint32_t base = sb + (i & 1) * STAGE;
        #pragma unroll
        for (int ks = 0; ks < 2; ks++) {
            uint32_t ah[MI][4], al[MI][4];
            #pragma unroll
            for (int mi = 0; mi < MI; mi++) {
                int q = lane >> 3, r = lane & 7;
                int row = wRow + mi * 16 + (q & 1) * 8 + r;
                int colb = (ks * 16 + (q >> 1) * 8) * 2;
                uint32_t ad = base + row * 80 + colb;
                ldm_x4(ah[mi], ad);
                ldm_x4(al[mi], ad + ATILE);
            }
            #pragma unroll
            for (int ni = 0; ni < 4; ni++) {
                int r = lane & 7, hf = (lane >> 3) & 1;
                int nrow = wCol + ni * 8 + r;
                int colb = (ks * 16 + hf * 8) * 2;
                uint32_t bd = base + 2 * ATILE + nrow * 80 + colb;
                uint32_t bh[2], bl[2];
                ldm_x2(bh, bd);
                ldm_x2(bl, bd + BTILE);
                #pragma unroll
                for (int mi = 0; mi < MI; mi++) {
                    mma_bf16(acc[mi][ni], ah[mi], bh);
                    mma_bf16(acc[mi][ni], ah[mi], bl);
                    mma_bf16(acc[mi][ni], al[mi], bh);
                }
            }
        }
        __syncthreads();
    }

    #pragma unroll
    for (int mi = 0; mi < MI; mi++) {
        int row0 = rowBase + wRow + mi * 16 + (lane >> 2);
        #pragma unroll
        for (int ni = 0; ni < 4; ni++) {
            int col = colBase + wCol + ni * 8 + (lane & 3) * 2;
            if (row0 < M)
                *(float2*)(g_h + (size_t)row0 * N + col) =
                    make_float2(acc[mi][ni][0], acc[mi][ni][1]);
            if (row0 + 8 < M)
                *(float2*)(g_h + (size_t)(row0 + 8) * N + col) =
                    make_float2(acc[mi][ni][2], acc[mi][ni][3]);
        }
    }
}

// ---------------- per-(node,head) attention logits, warp-per-unit, float4 ----------------
template <int C>
__global__ void k_alphas(const float* __restrict__ a_s, const float* __restrict__ a_d,
                         int N, int H) {
    int unit = (blockIdx.x * blockDim.x + threadIdx.x) >> 5;
    int lane = threadIdx.x & 31;
    if (unit >= N * H) return;
    int n = unit / H;
    int hh = unit - n * H;
    float s1 = 0.f, s2 = 0.f;
    if (lane < C / 4) {
        const float4* hp = (const float4*)(g_h + (size_t)n * H * C + hh * C);
        const float4* sp = (const float4*)(a_s + hh * C);
        const float4* dp = (const float4*)(a_d + hh * C);
        float4 v = hp[lane], a = sp[lane], b = dp[lane];
        s1 = v.x * a.x + v.y * a.y + v.z * a.z + v.w * a.w;
        s2 = v.x * b.x + v.y * b.y + v.z * b.z + v.w * b.w;
    }
    #pragma unroll
    for (int o = 16; o > 0; o >>= 1) {
        s1 += __shfl_xor_sync(0xffffffffu, s1, o);
        s2 += __shfl_xor_sync(0xffffffffu, s2, o);
    }
    if (lane == 0) {
        g_asrc[n * H + hh] = s1;
        g_adst[n * H + hh] = s2;
    }
}

// ---------------- fused softmax + aggregate + bias + relu (+ bf16 split) ----------------
// group of G = C/4 lanes per (node,head); float4 gather; edge loop unrolled x2.
template <int C, bool TO_OUT>
__global__ void __launch_bounds__(256) k_aggregate(
    const float* __restrict__ bias, float* __restrict__ outp, int N, int H) {
    constexpr int G = C / 4;
    int unit = (blockIdx.x * blockDim.x + threadIdx.x) / G;
    int l = threadIdx.x & (G - 1);
    if (unit >= N * H) return;
    int n = unit / H;
    int hh = unit - n * H;
    int HC = H * C;

    int s = g_rowptr[n];
    int e = g_rowptr[n + 1];
    float adn = g_adst[n * H + hh];

    // pass 1: lane-parallel max
    float m = -1e30f;
    for (int k = s + l; k < e; k += G) {
        int src = g_csr[k];
        float ev = g_asrc[src * H + hh] + adn;
        ev = (ev > 0.f) ? ev : NEG_SLOPE * ev;
        m = fmaxf(m, ev);
    }
    #pragma unroll
    for (int o = G / 2; o > 0; o >>= 1)
        m = fmaxf(m, __shfl_xor_sync(0xffffffffu, m, o, G));

    // pass 2: exp-sum + float4 weighted gather, 2 edges in flight
    float denom = 0.f;
    float4 acc = make_float4(0.f, 0.f, 0.f, 0.f);
    int k = s;
    for (; k + 1 < e; k += 2) {
        int sA = g_csr[k], sB = g_csr[k + 1];
        float aA = g_asrc[sA * H + hh], aB = g_asrc[sB * H + hh];
        float4 vA = ((const float4*)(g_h + (size_t)sA * HC + hh * C))[l];
        float4 vB = ((const float4*)(g_h + (size_t)sB * HC + hh * C))[l];
        float evA = aA + adn; evA = (evA > 0.f) ? evA : NEG_SLOPE * evA;
        float evB = aB + adn; evB = (evB > 0.f) ? evB : NEG_SLOPE * evB;
        float pA = __expf(evA - m), pB = __expf(evB - m);
        denom += pA + pB;
        acc.x += pA * vA.x + pB * vB.x;
        acc.y += pA * vA.y + pB * vB.y;
        acc.z += pA * vA.z + pB * vB.z;
        acc.w += pA * vA.w + pB * vB.w;
    }
    if (k < e) {
        int sA = g_csr[k];
        float aA = g_asrc[sA * H + hh];
        float4 vA = ((const float4*)(g_h + (size_t)sA * HC + hh * C))[l];
        float evA = aA + adn; evA = (evA > 0.f) ? evA : NEG_SLOPE * evA;
        float pA = __expf(evA - m);
        denom += pA;
        acc.x += pA * vA.x; acc.y += pA * vA.y; acc.z += pA * vA.z; acc.w += pA * vA.w;
    }

    float inv = 1.f / denom;
    const float4* bp = (const float4*)(bias + hh * C);
    float4 bv = bp[l];
    float4 r;
    r.x = fmaxf(acc.x * inv + bv.x, 0.f);
    r.y = fmaxf(acc.y * inv + bv.y, 0.f);
    r.z = fmaxf(acc.z * inv + bv.z, 0.f);
    r.w = fmaxf(acc.w * inv + bv.w, 0.f);

    size_t base = (size_t)n * HC + hh * C + l * 4;
    if (TO_OUT) {
        *(float4*)(outp + base) = r;
    } else {
        __nv_bfloat16 hx = __float2bfloat16(r.x), hy = __float2bfloat16(r.y);
        __nv_bfloat16 hz = __float2bfloat16(r.z), hw = __float2bfloat16(r.w);
        __nv_bfloat162* ph = (__nv_bfloat162*)(g_ah + base);
        ph[0] = __nv_bfloat162(hx, hy);
        ph[1] = __nv_bfloat162(hz, hw);
        __nv_bfloat162* pl = (__nv_bfloat162*)(g_al + base);
        pl[0] = __nv_bfloat162(__float2bfloat16(r.x - __bfloat162float(hx)),
                               __float2bfloat16(r.y - __bfloat162float(hy)));
        pl[1] = __nv_bfloat162(__float2bfloat16(r.z - __bfloat162float(hz)),
                               __float2bfloat16(r.w - __bfloat162float(hw)));
    }
}

// ---------------- driver ----------------
extern "C" void kernel_launch(void* const* d_in, const int* in_sizes, int n_in,
                              void* d_out, int out_size) {
    const float* x   = (const float*)d_in[0];
    const int*   ei  = (const int*)d_in[1];
    const float* W1  = (const float*)d_in[2];
    const float* a1s = (const float*)d_in[3];
    const float* a1d = (const float*)d_in[4];
    const float* b1  = (const float*)d_in[5];
    const float* W2  = (const float*)d_in[6];
    const float* a2s = (const float*)d_in[7];
    const float* a2d = (const float*)d_in[8];
    const float* b2  = (const float*)d_in[9];
    const float* W3  = (const float*)d_in[10];
    const float* a3s = (const float*)d_in[11];
    const float* a3d = (const float*)d_in[12];
    const float* b3  = (const float*)d_in[13];
    const float* W4  = (const float*)d_in[14];
    const float* a4s = (const float*)d_in[15];
    const float* a4d = (const float*)d_in[16];
    const float* b4  = (const float*)d_in[17];
    float* out = (float*)d_out;

    const int N = NN;
    const int E0 = in_sizes[1] / 2;
    const int MB = cdiv(N, 128);

    const int SMEM128 = 2 * (2 * 128 * 80 + 2 * 128 * 80);  // 81920
    const int SMEM64  = 2 * (2 * 128 * 80 + 2 * 64 * 80);   // 61440
    cudaFuncSetAttribute(k_mma<128, 2>, cudaFuncAttributeMaxDynamicSharedMemorySize, SMEM128);
    cudaFuncSetAttribute(k_mma<64, 4>,  cudaFuncAttributeMaxDynamicSharedMemorySize, SMEM64);

    // ---- all splits first (launches 1-5); k_mma layer 1 is launch #6 (ncu -s 5 -c 1) ----
    k_split_a<<<cdiv(N * 256, 256), 256>>>(x, N * 256);
    k_split_w<<<dim3(cdiv(512, 32), cdiv(256, 32)), dim3(32, 8)>>>(W1, 256, 512, WOF1);
    k_split_w<<<dim3(cdiv(512, 32), cdiv(512, 32)), dim3(32, 8)>>>(W2, 512, 512, WOF2);
    k_split_w<<<dim3(cdiv(256, 32), cdiv(512, 32)), dim3(32, 8)>>>(W3, 512, 256, WOF3);
    k_split_w<<<dim3(cdiv(64, 32), cdiv(256, 32)), dim3(32, 8)>>>(W4, 256, 64, WOF4);

    // ---- layer 1 GEMM (launch #6) ----
    k_mma<128, 2><<<dim3(4, MB), 256, SMEM128>>>(N, 512, 256, WOF1);

    // ---- CSR build (needed before first aggregate) ----
    k_init_deg<<<cdiv(N, 256), 256>>>(N);
    k_count<<<cdiv(E0, 256), 256>>>(ei, E0, N);
    k_scan<<<1, 1024>>>(N);
    k_place_self<<<cdiv(N, 256), 256>>>(N);
    k_scatter<<<cdiv(E0, 256), 256>>>(ei, E0, N);

    // ---- layer 1 edge phase ----
    k_alphas<128><<<cdiv(N * 4, 8), 256>>>(a1s, a1d, N, 4);
    k_aggregate<128, false><<<cdiv(N * 4, 8), 256>>>(b1, nullptr, N, 4);

    // ---- layer 2 ----
    k_mma<128, 2><<<dim3(4, MB), 256, SMEM128>>>(N, 512, 512, WOF2);
    k_alphas<128><<<cdiv(N * 4, 8), 256>>>(a2s, a2d, N, 4);
    k_aggregate<128, false><<<cdiv(N * 4, 8), 256>>>(b2, nullptr, N, 4);

    // ---- layer 3 ----
    k_mma<128, 2><<<dim3(2, MB), 256, SMEM128>>>(N, 256, 512, WOF3);
    k_alphas<64><<<cdiv(N * 4, 8), 256>>>(a3s, a3d, N, 4);
    k_aggregate<64, false><<<cdiv(N * 4, 16), 256>>>(b3, nullptr, N, 4);

    // ---- layer 4 ----
    k_mma<64, 4><<<dim3(1, MB), 256, SMEM64>>>(N, 64, 256, WOF4);
    k_alphas<64><<<cdiv(N * 1, 8), 256>>>(a4s, a4d, N, 1);
    k_aggregate<64, true><<<cdiv(N * 1, 16), 256>>>(b4, out, N, 1);
}